// round 9
// baseline (speedup 1.0000x reference)
#include <cuda_runtime.h>
#include <cuda_fp16.h>
#include <cstdint>

#define TILE_M   128
#define NTHREADS 512

// ---- SMEM layout (bytes) ----
#define SM_A0    0          // 2 stages x 128 rows x 256B fp16 (swizzled 16B chunks)
#define SM_AST   32768
#define SM_W     65536      // 128 x 128 fp16, same swizzled layout, [n][k]
#define SM_TRANS 98304      // 16 warps x 32x36 f32 staging (4608B each)
#define SM_BIAS  172032     // 128 f32
#define SM_TOT   172544

__device__ int g_idx_is64;

// Index dtype sniffing: int64 indices (< 2^31, non-negative) have all-zero high
// words; int32 data at odd word positions is ~never all-zero for 64 samples.
__global__ void detect_idx_kernel(const unsigned int* __restrict__ w) {
    if (threadIdx.x == 0) {
        int is64 = 1;
        for (int i = 0; i < 64; i++)
            if (w[2 * i + 1] != 0u) { is64 = 0; break; }
        g_idx_is64 = is64;
    }
}

__device__ __forceinline__ uint32_t smem_u32(const void* p) {
    return (uint32_t)__cvta_generic_to_shared(p);
}
// swizzled byte offset of 16B chunk `chunk` in row `row` (256B rows)
__device__ __forceinline__ uint32_t sw(int row, int chunk) {
    return (uint32_t)((row << 8) + ((chunk ^ (row & 7)) << 4));
}
__device__ __forceinline__ uint32_t f2h2(float a, float b) {
    __half2 h = __floats2half2_rn(a, b);
    return *reinterpret_cast<uint32_t*>(&h);
}
__device__ __forceinline__ void ldsm4(uint32_t r[4], uint32_t addr) {
    asm volatile("ldmatrix.sync.aligned.m8n8.x4.shared.b16 {%0,%1,%2,%3}, [%4];"
                 : "=r"(r[0]), "=r"(r[1]), "=r"(r[2]), "=r"(r[3]) : "r"(addr));
}
__device__ __forceinline__ void mma_f16(float c[4], const uint32_t a[4],
                                        uint32_t b0, uint32_t b1) {
    asm volatile(
        "mma.sync.aligned.m16n8k16.row.col.f32.f16.f16.f32 "
        "{%0,%1,%2,%3}, {%4,%5,%6,%7}, {%8,%9}, {%0,%1,%2,%3};\n"
        : "+f"(c[0]), "+f"(c[1]), "+f"(c[2]), "+f"(c[3])
        : "r"(a[0]), "r"(a[1]), "r"(a[2]), "r"(a[3]), "r"(b0), "r"(b1));
}

__global__ void __launch_bounds__(NTHREADS, 1)
edge_encoder_kernel(const float* __restrict__ x,
                    const float* __restrict__ ea,
                    const void* __restrict__ idx,
                    const float* __restrict__ Wg,
                    const float* __restrict__ bg,
                    float* __restrict__ out,
                    int E, int ntiles) {
    extern __shared__ char smem[];
    const uint32_t sb = smem_u32(smem);
    const int tid  = threadIdx.x;
    const int lane = tid & 31;
    const int warp = tid >> 5;
    const int g    = lane >> 2;
    const int tig  = lane & 3;
    const int wm   = warp >> 2;   // 0..3 (32-row slab)
    const int wn   = warp & 3;    // 0..3 (32-col slab)
    const int is64 = g_idx_is64;

    // gather lane roles: part 0,1 = x row halves (128B each); 2,3 = ea halves
    const int part = lane >> 3;   // 0..3
    const int off  = lane & 7;    // 16B chunk within 128B half

    // ---- stage W as fp16 (RN) into swizzled [n][k] layout, plus bias ----
    for (int p = tid; p < 8192; p += NTHREADS) {     // 8192 half2 pairs
        int n = p >> 6, kp = p & 63;                 // k = 2*kp
        float2 w2 = *(const float2*)&Wg[n * 128 + 2 * kp];
        *(uint32_t*)(smem + SM_W + sw(n, kp >> 2) + (kp & 3) * 4) = f2h2(w2.x, w2.y);
    }
    float* Bs = (float*)(smem + SM_BIAS);
    if (tid < 128) Bs[tid] = bg[tid];

    // ---- coalesced gather: warp covers one edge-row per round (8 rounds) ----
    auto gather = [&](float4 gb[8], long tile) {
        #pragma unroll
        for (int p = 0; p < 8; p++) {
            long e  = tile * TILE_M + (p * 16 + warp);
            long ec = e < (long)E ? e : (long)(E - 1);
            long long r = 0;
            if (lane == 0)
                r = is64 ? ((const long long*)idx)[ec]
                         : (long long)((const int*)idx)[ec];
            r = __shfl_sync(0xffffffffu, r, 0);
            const float* src = (part < 2) ? (x + ((long)r << 6)) : (ea + (ec << 6));
            gb[p] = *(const float4*)(src + (part & 1) * 32 + off * 4);
        }
    };
    auto cvtSTS = [&](const float4 gb[8], int stage) {
        #pragma unroll
        for (int p = 0; p < 8; p++) {
            int row = p * 16 + warp;
            uint2 o;
            o.x = f2h2(gb[p].x, gb[p].y);
            o.y = f2h2(gb[p].z, gb[p].w);
            *(uint2*)(smem + SM_A0 + stage * SM_AST +
                      sw(row, part * 4 + (off >> 1)) + (off & 1) * 8) = o;
        }
    };

    const long stride = gridDim.x;
    const long tile0  = blockIdx.x;

    // prologue: gather tile0 into stage 0
    {
        float4 gb[8];
        gather(gb, tile0);
        cvtSTS(gb, 0);
    }
    __syncthreads();   // W / bias / stage 0 visible

    // hoisted bias (cols wn*32 + nn*8 + 2*tig)
    float2 bb[4];
    #pragma unroll
    for (int nn = 0; nn < 4; nn++) {
        int col = wn * 32 + nn * 8 + 2 * tig;
        bb[nn] = make_float2(Bs[col], Bs[col + 1]);
    }

    // per-warp ldmatrix lane terms
    const int r7  = lane & 7;
    const int hiA = lane >> 4;                      // 0/1
    const int hiB = (lane >> 3) & 1;                // 0/1
    const uint32_t aRowOff = (uint32_t)((wm * 32 + (lane & 15)) << 8);
    const uint32_t bBase0  = sb + SM_W +
        (uint32_t)((wn * 32 + (lane & 7) + ((lane >> 4) << 3)) << 8);
    const uint32_t bBase1  = bBase0 + (16 << 8);

    // per-warp transpose staging (32 rows x 36 f32)
    float* tb = (float*)(smem + SM_TRANS + warp * 4608);
    const int orow = lane >> 3;    // 0..3: row group for store phase
    const int och  = lane & 7;     // 0..7: 16B column chunk

    int s = 0;
    for (long tile = tile0; tile < ntiles; tile += stride, s ^= 1) {
        long next = tile + stride;
        const bool hasNext = next < ntiles;
        float4 gb[8];
        if (hasNext) gather(gb, next);              // latency hidden by compute

        const uint32_t aBase = sb + SM_A0 + s * SM_AST + aRowOff;

        float c[2][4][4];
        #pragma unroll
        for (int mb = 0; mb < 2; mb++)
            #pragma unroll
            for (int nn = 0; nn < 4; nn++)
                #pragma unroll
                for (int q = 0; q < 4; q++) c[mb][nn][q] = 0.f;

        #pragma unroll
        for (int ks = 0; ks < 8; ks++) {
            uint32_t a0[4], a1[4], b0[4], b1[4];
            uint32_t ca = (uint32_t)(((2 * ks + hiA) ^ r7) << 4);
            uint32_t cb = (uint32_t)(((2 * ks + hiB) ^ r7) << 4);
            ldsm4(a0, aBase + ca);
            ldsm4(a1, aBase + (16 << 8) + ca);
            ldsm4(b0, bBase0 + cb);
            ldsm4(b1, bBase1 + cb);
            mma_f16(c[0][0], a0, b0[0], b0[1]);
            mma_f16(c[0][1], a0, b0[2], b0[3]);
            mma_f16(c[0][2], a0, b1[0], b1[1]);
            mma_f16(c[0][3], a0, b1[2], b1[3]);
            mma_f16(c[1][0], a1, b0[0], b0[1]);
            mma_f16(c[1][1], a1, b0[2], b0[3]);
            mma_f16(c[1][2], a1, b1[0], b1[1]);
            mma_f16(c[1][3], a1, b1[2], b1[3]);
        }

        // write next A stage early so STS drain overlaps epilogue
        if (hasNext) cvtSTS(gb, s ^ 1);

        // ---- transposing epilogue: frags -> per-warp SMEM -> coalesced STG.128 ----
        #pragma unroll
        for (int mb = 0; mb < 2; mb++)
            #pragma unroll
            for (int hh = 0; hh < 2; hh++) {
                int lrow = mb * 16 + hh * 8 + g;
                #pragma unroll
                for (int nn = 0; nn < 4; nn++) {
                    float v0 = fmaxf(c[mb][nn][2 * hh + 0] + bb[nn].x, 0.f);
                    float v1 = fmaxf(c[mb][nn][2 * hh + 1] + bb[nn].y, 0.f);
                    *(float2*)&tb[lrow * 36 + nn * 8 + 2 * tig] = make_float2(v0, v1);
                }
            }
        __syncwarp();
        #pragma unroll
        for (int it = 0; it < 8; it++) {
            int lrow = it * 4 + orow;
            long e = tile * TILE_M + wm * 32 + lrow;
            if (e < E) {
                float4 v = *(float4*)&tb[lrow * 36 + och * 4];
                *(float4*)&out[e * 128 + wn * 32 + och * 4] = v;
            }
        }
        __syncwarp();      // tb reusable next tile
        __syncthreads();   // stage s^1 visible; stage s free for refill
    }
}

extern "C" void kernel_launch(void* const* d_in, const int* in_sizes, int n_in,
                              void* d_out, int out_size) {
    const float* x   = (const float*)d_in[0];
    const float* ea  = (const float*)d_in[1];
    const void*  idx = d_in[2];
    const float* W   = (const float*)d_in[3];
    const float* b   = (const float*)d_in[4];
    float* out = (float*)d_out;

    int E = in_sizes[1] / 64;                  // edge_attr is [E, 64]
    int ntiles = (E + TILE_M - 1) / TILE_M;

    int dev = 0, sms = 148;
    cudaGetDevice(&dev);
    cudaDeviceGetAttribute(&sms, cudaDevAttrMultiProcessorCount, dev);

    cudaFuncSetAttribute(edge_encoder_kernel,
                         cudaFuncAttributeMaxDynamicSharedMemorySize, SM_TOT);

    detect_idx_kernel<<<1, 32>>>((const unsigned int*)idx);

    int grid = sms < ntiles ? sms : ntiles;
    edge_encoder_kernel<<<grid, NTHREADS, SM_TOT>>>(x, ea, idx, W, b, out, E, ntiles);
}

// round 14
// speedup vs baseline: 1.5309x; 1.5309x over previous
#include <cuda_runtime.h>
#include <cuda_fp16.h>
#include <cstdint>

#define TILE_M   128
#define NTHREADS 512

// ---- SMEM layout (bytes) ----
#define SM_A0    0          // 2 stages x 128 rows x 256B fp16 (swizzled 16B chunks)
#define SM_AST   32768
#define SM_W     65536      // 128 x 128 fp16, same swizzled layout, [n][k]
#define SM_TRANS 98304      // 16 warps x 32x36 f32 staging (4608B each)
#define SM_BIAS  172032     // 128 f32
#define SM_TOT   172544

__device__ int g_idx_is64;

// Index dtype sniffing: int64 indices (< 2^31, non-negative) have all-zero high
// words; int32 data at odd word positions is ~never all-zero for 64 samples.
__global__ void detect_idx_kernel(const unsigned int* __restrict__ w) {
    if (threadIdx.x == 0) {
        int is64 = 1;
        for (int i = 0; i < 64; i++)
            if (w[2 * i + 1] != 0u) { is64 = 0; break; }
        g_idx_is64 = is64;
    }
}

__device__ __forceinline__ uint32_t smem_u32(const void* p) {
    return (uint32_t)__cvta_generic_to_shared(p);
}
// swizzled byte offset of 16B chunk `chunk` in row `row` (256B rows)
__device__ __forceinline__ uint32_t sw(int row, int chunk) {
    return (uint32_t)((row << 8) + ((chunk ^ (row & 7)) << 4));
}
__device__ __forceinline__ uint32_t f2h2(float a, float b) {
    __half2 h = __floats2half2_rn(a, b);
    return *reinterpret_cast<uint32_t*>(&h);
}
__device__ __forceinline__ void ldsm4(uint32_t r[4], uint32_t addr) {
    asm volatile("ldmatrix.sync.aligned.m8n8.x4.shared.b16 {%0,%1,%2,%3}, [%4];"
                 : "=r"(r[0]), "=r"(r[1]), "=r"(r[2]), "=r"(r[3]) : "r"(addr));
}
__device__ __forceinline__ void mma_f16(float c[4], const uint32_t a[4],
                                        uint32_t b0, uint32_t b1) {
    asm volatile(
        "mma.sync.aligned.m16n8k16.row.col.f32.f16.f16.f32 "
        "{%0,%1,%2,%3}, {%4,%5,%6,%7}, {%8,%9}, {%0,%1,%2,%3};\n"
        : "+f"(c[0]), "+f"(c[1]), "+f"(c[2]), "+f"(c[3])
        : "r"(a[0]), "r"(a[1]), "r"(a[2]), "r"(a[3]), "r"(b0), "r"(b1));
}

__global__ void __launch_bounds__(NTHREADS, 1)
edge_encoder_kernel(const float* __restrict__ x,
                    const float* __restrict__ ea,
                    const void* __restrict__ idx,
                    const float* __restrict__ Wg,
                    const float* __restrict__ bg,
                    float* __restrict__ out,
                    int E, int ntiles) {
    extern __shared__ char smem[];
    const uint32_t sb = smem_u32(smem);
    const int tid  = threadIdx.x;
    const int lane = tid & 31;
    const int warp = tid >> 5;
    const int g    = lane >> 2;
    const int tig  = lane & 3;
    const int wm   = warp >> 2;   // 0..3 (32-row slab)
    const int wn   = warp & 3;    // 0..3 (32-col slab)
    const int is64 = g_idx_is64;

    // gather lane roles: part 0,1 = x row halves (128B each); 2,3 = ea halves
    const int part = lane >> 3;   // 0..3
    const int off  = lane & 7;    // 16B chunk within 128B half

    // ---- stage W as fp16 (RN) into swizzled [n][k] layout, plus bias ----
    for (int p = tid; p < 8192; p += NTHREADS) {     // 8192 half2 pairs
        int n = p >> 6, kp = p & 63;                 // k = 2*kp
        float2 w2 = *(const float2*)&Wg[n * 128 + 2 * kp];
        *(uint32_t*)(smem + SM_W + sw(n, kp >> 2) + (kp & 3) * 4) = f2h2(w2.x, w2.y);
    }
    float* Bs = (float*)(smem + SM_BIAS);
    if (tid < 128) Bs[tid] = bg[tid];

    // ---- coalesced gather, warp covers one edge-row per round (8 rounds) ----
    // Phase 1: all lanes load the round's index directly (same address ->
    // broadcast, 1 wavefront) — 8 independent loads in flight, no shfl chain.
    // Indices < 2^31 so the low 32-bit word suffices for both int32/int64.
    const int* idx32 = (const int*)idx;
    auto gather = [&](float4 gb[8], long tile) {
        int ri[8];
        #pragma unroll
        for (int p = 0; p < 8; p++) {
            long e  = tile * TILE_M + (p * 16 + warp);
            long ec = e < (long)E ? e : (long)(E - 1);
            ri[p] = idx32[is64 ? (ec << 1) : ec];
        }
        #pragma unroll
        for (int p = 0; p < 8; p++) {
            long e  = tile * TILE_M + (p * 16 + warp);
            long ec = e < (long)E ? e : (long)(E - 1);
            const float* src = (part < 2) ? (x + ((long)ri[p] << 6))
                                          : (ea + (ec << 6));
            gb[p] = *(const float4*)(src + (part & 1) * 32 + off * 4);
        }
    };
    auto cvtSTS = [&](const float4 gb[8], int stage) {
        #pragma unroll
        for (int p = 0; p < 8; p++) {
            int row = p * 16 + warp;
            uint2 o;
            o.x = f2h2(gb[p].x, gb[p].y);
            o.y = f2h2(gb[p].z, gb[p].w);
            *(uint2*)(smem + SM_A0 + stage * SM_AST +
                      sw(row, part * 4 + (off >> 1)) + (off & 1) * 8) = o;
        }
    };

    const long stride = gridDim.x;
    const long tile0  = blockIdx.x;

    // prologue: gather tile0 into stage 0
    {
        float4 gb[8];
        gather(gb, tile0);
        cvtSTS(gb, 0);
    }
    __syncthreads();   // W / bias / stage 0 visible

    // hoisted bias (cols wn*32 + nn*8 + 2*tig)
    float2 bb[4];
    #pragma unroll
    for (int nn = 0; nn < 4; nn++) {
        int col = wn * 32 + nn * 8 + 2 * tig;
        bb[nn] = make_float2(Bs[col], Bs[col + 1]);
    }

    // per-warp ldmatrix lane terms
    const int r7  = lane & 7;
    const int hiA = lane >> 4;                      // 0/1
    const int hiB = (lane >> 3) & 1;                // 0/1
    const uint32_t aRowOff = (uint32_t)((wm * 32 + (lane & 15)) << 8);
    const uint32_t bBase0  = sb + SM_W +
        (uint32_t)((wn * 32 + (lane & 7) + ((lane >> 4) << 3)) << 8);
    const uint32_t bBase1  = bBase0 + (16 << 8);

    // per-warp transpose staging (32 rows x 36 f32)
    float* tb = (float*)(smem + SM_TRANS + warp * 4608);
    const int orow = lane >> 3;    // 0..3: row group for store phase
    const int och  = lane & 7;     // 0..7: 16B column chunk

    int s = 0;
    for (long tile = tile0; tile < ntiles; tile += stride, s ^= 1) {
        long next = tile + stride;
        const bool hasNext = next < ntiles;
        float4 gb[8];
        if (hasNext) gather(gb, next);              // latency hidden by compute

        const uint32_t aBase = sb + SM_A0 + s * SM_AST + aRowOff;

        float c[2][4][4];
        #pragma unroll
        for (int mb = 0; mb < 2; mb++)
            #pragma unroll
            for (int nn = 0; nn < 4; nn++)
                #pragma unroll
                for (int q = 0; q < 4; q++) c[mb][nn][q] = 0.f;

        #pragma unroll
        for (int ks = 0; ks < 8; ks++) {
            uint32_t a0[4], a1[4], b0[4], b1[4];
            uint32_t ca = (uint32_t)(((2 * ks + hiA) ^ r7) << 4);
            uint32_t cb = (uint32_t)(((2 * ks + hiB) ^ r7) << 4);
            ldsm4(a0, aBase + ca);
            ldsm4(a1, aBase + (16 << 8) + ca);
            ldsm4(b0, bBase0 + cb);
            ldsm4(b1, bBase1 + cb);
            mma_f16(c[0][0], a0, b0[0], b0[1]);
            mma_f16(c[0][1], a0, b0[2], b0[3]);
            mma_f16(c[0][2], a0, b1[0], b1[1]);
            mma_f16(c[0][3], a0, b1[2], b1[3]);
            mma_f16(c[1][0], a1, b0[0], b0[1]);
            mma_f16(c[1][1], a1, b0[2], b0[3]);
            mma_f16(c[1][2], a1, b1[0], b1[1]);
            mma_f16(c[1][3], a1, b1[2], b1[3]);
        }

        // write next A stage early so STS drain overlaps epilogue
        if (hasNext) cvtSTS(gb, s ^ 1);

        // ---- transposing epilogue: frags -> per-warp SMEM -> coalesced STG.128 ----
        #pragma unroll
        for (int mb = 0; mb < 2; mb++)
            #pragma unroll
            for (int hh = 0; hh < 2; hh++) {
                int lrow = mb * 16 + hh * 8 + g;
                #pragma unroll
                for (int nn = 0; nn < 4; nn++) {
                    float v0 = fmaxf(c[mb][nn][2 * hh + 0] + bb[nn].x, 0.f);
                    float v1 = fmaxf(c[mb][nn][2 * hh + 1] + bb[nn].y, 0.f);
                    *(float2*)&tb[lrow * 36 + nn * 8 + 2 * tig] = make_float2(v0, v1);
                }
            }
        __syncwarp();
        #pragma unroll
        for (int it = 0; it < 8; it++) {
            int lrow = it * 4 + orow;
            long e = tile * TILE_M + wm * 32 + lrow;
            if (e < E) {
                float4 v = *(float4*)&tb[lrow * 36 + och * 4];
                *(float4*)&out[e * 128 + wn * 32 + och * 4] = v;
            }
        }
        __syncwarp();      // tb reusable next tile
        __syncthreads();   // stage s^1 visible; stage s free for refill
    }
}

extern "C" void kernel_launch(void* const* d_in, const int* in_sizes, int n_in,
                              void* d_out, int out_size) {
    const float* x   = (const float*)d_in[0];
    const float* ea  = (const float*)d_in[1];
    const void*  idx = d_in[2];
    const float* W   = (const float*)d_in[3];
    const float* b   = (const float*)d_in[4];
    float* out = (float*)d_out;

    int E = in_sizes[1] / 64;                  // edge_attr is [E, 64]
    int ntiles = (E + TILE_M - 1) / TILE_M;

    int dev = 0, sms = 148;
    cudaGetDevice(&dev);
    cudaDeviceGetAttribute(&sms, cudaDevAttrMultiProcessorCount, dev);

    cudaFuncSetAttribute(edge_encoder_kernel,
                         cudaFuncAttributeMaxDynamicSharedMemorySize, SM_TOT);

    detect_idx_kernel<<<1, 32>>>((const unsigned int*)idx);

    int grid = sms < ntiles ? sms : ntiles;
    edge_encoder_kernel<<<grid, NTHREADS, SM_TOT>>>(x, ea, idx, W, b, out, E, ntiles);
}